// round 4
// baseline (speedup 1.0000x reference)
#include <cuda_runtime.h>
#include <cuda_bf16.h>

#define N_NODES 100000
#define N_EDGES 1600000
#define TOT_E   (N_EDGES + N_NODES)   // edges + self loops
#define SCAN_NB 98                     // ceil(100000/1024)

// ---------------- scratch (__device__ globals; no allocations) ----------------
__device__ int    g_cur[N_NODES];
__device__ int    g_rowptr[N_NODES + 1];
__device__ int    g_csr[TOT_E];
__device__ int    g_bsum[SCAN_NB];
__device__ float  g_h1[N_NODES * 128];
__device__ float  g_out1[N_NODES * 128];
__device__ float  g_h2[N_NODES * 128];
__device__ float2 g_alpha[TOT_E];
__device__ float  g_as1[N_NODES * 2], g_ad1[N_NODES * 2];
__device__ float  g_as2[N_NODES * 2], g_ad2[N_NODES * 2];
__device__ float  g_colsum[128], g_colsq[128];
__device__ float  g_W2p[128 * 128];
__device__ float  g_biasEff[128];
__device__ float  g_attS2p[128], g_attD2p[128];

// ---------------- CSR build ----------------
__global__ void init_k() {
    int i = blockIdx.x * blockDim.x + threadIdx.x;
    if (i < N_NODES) g_cur[i] = 1;          // self loop
    if (i < 128) { g_colsum[i] = 0.f; g_colsq[i] = 0.f; }
}

__global__ void count_k(const int* __restrict__ ei) {
    int e = blockIdx.x * blockDim.x + threadIdx.x;
    if (e < N_EDGES) atomicAdd(&g_cur[ei[N_EDGES + e]], 1);
}

__global__ void scan1_k() {
    __shared__ int sh[1024];
    int i = blockIdx.x * 1024 + threadIdx.x;
    int v = (i < N_NODES) ? g_cur[i] : 0;
    sh[threadIdx.x] = v;
    __syncthreads();
    for (int off = 1; off < 1024; off <<= 1) {
        int t = (threadIdx.x >= off) ? sh[threadIdx.x - off] : 0;
        __syncthreads();
        sh[threadIdx.x] += t;
        __syncthreads();
    }
    if (i < N_NODES) g_rowptr[i] = sh[threadIdx.x] - v;   // local exclusive
    if (threadIdx.x == 1023) g_bsum[blockIdx.x] = sh[1023];
}

__global__ void scan2_k() {
    if (threadIdx.x == 0) {
        int a = 0;
        for (int k = 0; k < SCAN_NB; k++) { int t = g_bsum[k]; g_bsum[k] = a; a += t; }
    }
}

__global__ void scan3_k() {
    int i = blockIdx.x * 1024 + threadIdx.x;
    if (i < N_NODES) {
        int r = g_rowptr[i] + g_bsum[blockIdx.x];
        g_rowptr[i] = r;
        g_cur[i]    = r;
    }
    if (i == 0) g_rowptr[N_NODES] = TOT_E;
}

__global__ void fill_k(const int* __restrict__ ei) {
    int idx = blockIdx.x * blockDim.x + threadIdx.x;
    if (idx >= TOT_E) return;
    int s, d;
    if (idx < N_EDGES) { s = ei[idx]; d = ei[N_EDGES + idx]; }
    else               { s = d = idx - N_EDGES; }
    int p = atomicAdd(&g_cur[d], 1);
    g_csr[p] = s;
}

// ---------------- GEMM: [N,128] @ [128,128] + bias ----------------
// L==1: A=x, W=W1, bias=b1, out=g_h1
// L==2: A=g_out1, W=g_W2p, bias=g_biasEff, out=g_h2
template <int L>
__global__ __launch_bounds__(256) void gemm_k(const float* __restrict__ A_in,
                                              const float* __restrict__ W_in,
                                              const float* __restrict__ B_in) {
    const float* __restrict__ A = (L == 1) ? A_in : g_out1;
    const float* __restrict__ W = (L == 1) ? W_in : g_W2p;
    const float* __restrict__ B = (L == 1) ? B_in : g_biasEff;
    float* __restrict__ C       = (L == 1) ? g_h1 : g_h2;

    __shared__ float Ws[32][128];
    __shared__ float Xs[64][32];
    int tid = threadIdx.x;
    int tx = tid & 31, ty = tid >> 5;
    int row0 = blockIdx.x * 64;

    float acc[8][4];
#pragma unroll
    for (int i = 0; i < 8; i++) { acc[i][0] = acc[i][1] = acc[i][2] = acc[i][3] = 0.f; }

    for (int kk = 0; kk < 128; kk += 32) {
#pragma unroll
        for (int l = 0; l < 4; l++) {            // Ws: 32x128 floats
            int f = (l * 256 + tid) * 4;
            int r = f >> 7, c = f & 127;
            *(float4*)&Ws[r][c] = *(const float4*)&W[(kk + r) * 128 + c];
        }
#pragma unroll
        for (int l = 0; l < 2; l++) {            // Xs: 64x32 floats
            int f = (l * 256 + tid) * 4;
            int r = f >> 5, c = f & 31;
            int gr = row0 + r;
            float4 v = make_float4(0.f, 0.f, 0.f, 0.f);
            if (gr < N_NODES) v = *(const float4*)&A[gr * 128 + kk + c];
            *(float4*)&Xs[r][c] = v;
        }
        __syncthreads();
#pragma unroll
        for (int k = 0; k < 32; k++) {
            float4 bv = *(float4*)&Ws[k][tx * 4];
#pragma unroll
            for (int i = 0; i < 8; i++) {
                float a = Xs[ty * 8 + i][k];
                acc[i][0] += a * bv.x; acc[i][1] += a * bv.y;
                acc[i][2] += a * bv.z; acc[i][3] += a * bv.w;
            }
        }
        __syncthreads();
    }
    float4 bv = *(const float4*)&B[tx * 4];
#pragma unroll
    for (int i = 0; i < 8; i++) {
        int r = row0 + ty * 8 + i;
        if (r < N_NODES) {
            float4 o = make_float4(acc[i][0] + bv.x, acc[i][1] + bv.y,
                                   acc[i][2] + bv.z, acc[i][3] + bv.w);
            *(float4*)&C[r * 128 + tx * 4] = o;
        }
    }
}

// ---------------- attention dot products: a_src/a_dst per node/head ----------------
template <int L>
__global__ __launch_bounds__(256) void att_k(const float* __restrict__ S_in,
                                             const float* __restrict__ D_in) {
    int gw = (blockIdx.x * blockDim.x + threadIdx.x) >> 5;
    int lane = threadIdx.x & 31;
    if (gw >= N_NODES) return;
    const float* __restrict__ h = (L == 1) ? g_h1 : g_h2;
    const float* __restrict__ S = (L == 1) ? S_in : g_attS2p;
    const float* __restrict__ D = (L == 1) ? D_in : g_attD2p;
    float* __restrict__ as = (L == 1) ? g_as1 : g_as2;
    float* __restrict__ ad = (L == 1) ? g_ad1 : g_ad2;

    float4 hv = *(const float4*)&h[gw * 128 + lane * 4];
    float4 s4 = *(const float4*)&S[lane * 4];
    float4 d4 = *(const float4*)&D[lane * 4];
    float ps = hv.x * s4.x + hv.y * s4.y + hv.z * s4.z + hv.w * s4.w;
    float pd = hv.x * d4.x + hv.y * d4.y + hv.z * d4.z + hv.w * d4.w;
#pragma unroll
    for (int off = 8; off; off >>= 1) {          // reduce within 16-lane halves
        ps += __shfl_xor_sync(0xffffffffu, ps, off);
        pd += __shfl_xor_sync(0xffffffffu, pd, off);
    }
    if (lane == 0)  { as[gw * 2]     = ps; ad[gw * 2]     = pd; }
    if (lane == 16) { as[gw * 2 + 1] = ps; ad[gw * 2 + 1] = pd; }
}

// ---------------- warp-per-node GAT aggregation ----------------
// L==1: out1[n][128] = agg + b1   (bias = b1)
// L==2: d_out[n][40] = log_softmax(mean_heads(agg) + b2)   (bias = b2, out param)
template <int L>
__global__ __launch_bounds__(256) void agg_k(const float* __restrict__ bias,
                                             float* __restrict__ out_final) {
    int gw = (blockIdx.x * blockDim.x + threadIdx.x) >> 5;
    int lane = threadIdx.x & 31;
    if (gw >= N_NODES) return;
    const float* __restrict__ h  = (L == 1) ? g_h1 : g_h2;
    const float* __restrict__ as = (L == 1) ? g_as1 : g_as2;
    const float* __restrict__ ad = (L == 1) ? g_ad1 : g_ad2;

    int n = gw;
    int beg = g_rowptr[n], end = g_rowptr[n + 1];
    float ad0 = ad[n * 2], ad1 = ad[n * 2 + 1];

    // pass 1: alpha = leaky_relu(a_src[s] + a_dst[n]); store + per-head max
    float m0 = -1e30f, m1 = -1e30f;
    for (int i = beg + lane; i < end; i += 32) {
        int s = g_csr[i];
        float2 a = *(const float2*)&as[s * 2];
        float x0 = a.x + ad0; x0 = x0 > 0.f ? x0 : 0.2f * x0;
        float x1 = a.y + ad1; x1 = x1 > 0.f ? x1 : 0.2f * x1;
        g_alpha[i] = make_float2(x0, x1);
        m0 = fmaxf(m0, x0); m1 = fmaxf(m1, x1);
    }
#pragma unroll
    for (int off = 16; off; off >>= 1) {
        m0 = fmaxf(m0, __shfl_xor_sync(0xffffffffu, m0, off));
        m1 = fmaxf(m1, __shfl_xor_sync(0xffffffffu, m1, off));
    }
    // pass 2: e = exp(alpha - max); store + per-head sum
    float d0 = 0.f, d1 = 0.f;
    for (int i = beg + lane; i < end; i += 32) {
        float2 a = g_alpha[i];
        float e0 = __expf(a.x - m0), e1 = __expf(a.y - m1);
        g_alpha[i] = make_float2(e0, e1);
        d0 += e0; d1 += e1;
    }
#pragma unroll
    for (int off = 16; off; off >>= 1) {
        d0 += __shfl_xor_sync(0xffffffffu, d0, off);
        d1 += __shfl_xor_sync(0xffffffffu, d1, off);
    }
    float inv = (lane < 16) ? (1.0f / d0) : (1.0f / d1);

    // pass 3: weighted gather-accumulate, whole warp per edge (coalesced 512B rows)
    int col = lane * 4;
    float a0 = 0.f, a1 = 0.f, a2 = 0.f, a3 = 0.f;
    for (int i = beg; i < end; i++) {
        int s = g_csr[i];
        float2 e = g_alpha[i];
        float w = (lane < 16 ? e.x : e.y) * inv;
        float4 hv = *(const float4*)&h[s * 128 + col];
        a0 += w * hv.x; a1 += w * hv.y; a2 += w * hv.z; a3 += w * hv.w;
    }

    if (L == 1) {
        float4 bv = *(const float4*)&bias[col];
        float4 o = make_float4(a0 + bv.x, a1 + bv.y, a2 + bv.z, a3 + bv.w);
        *(float4*)&g_out1[n * 128 + col] = o;
    } else {
        // pair heads: head0 col c in lane c/4; head1 col c (at 64+c) in lane 16+c/4
        float p0 = __shfl_down_sync(0xffffffffu, a0, 16);
        float p1 = __shfl_down_sync(0xffffffffu, a1, 16);
        float p2 = __shfl_down_sync(0xffffffffu, a2, 16);
        float p3 = __shfl_down_sync(0xffffffffu, a3, 16);
        bool valid = (lane < 10);                 // cols lane*4..+3 all < 40
        float z0 = -1e30f, z1 = -1e30f, z2 = -1e30f, z3 = -1e30f;
        if (valid) {
            float4 b2v = *(const float4*)&bias[lane * 4];
            z0 = 0.5f * (a0 + p0) + b2v.x;
            z1 = 0.5f * (a1 + p1) + b2v.y;
            z2 = 0.5f * (a2 + p2) + b2v.z;
            z3 = 0.5f * (a3 + p3) + b2v.w;
        }
        float mx = fmaxf(fmaxf(z0, z1), fmaxf(z2, z3));
#pragma unroll
        for (int off = 16; off; off >>= 1)
            mx = fmaxf(mx, __shfl_xor_sync(0xffffffffu, mx, off));
        float se = 0.f;
        if (valid)
            se = __expf(z0 - mx) + __expf(z1 - mx) + __expf(z2 - mx) + __expf(z3 - mx);
#pragma unroll
        for (int off = 16; off; off >>= 1)
            se += __shfl_xor_sync(0xffffffffu, se, off);
        float lse = __logf(se) + mx;
        if (valid) {
            float4 o = make_float4(z0 - lse, z1 - lse, z2 - lse, z3 - lse);
            *(float4*)&out_final[n * 40 + lane * 4] = o;
        }
    }
}

// ---------------- BatchNorm stats over g_out1 ----------------
__global__ void bn_stats_k() {
    int lane = threadIdx.x;   // 0..31 -> 4 columns each
    int wy = threadIdx.y;     // 0..7
    float s0 = 0, s1 = 0, s2 = 0, s3 = 0, q0 = 0, q1 = 0, q2 = 0, q3 = 0;
    for (int n = blockIdx.x * 8 + wy; n < N_NODES; n += gridDim.x * 8) {
        float4 v = *(const float4*)&g_out1[n * 128 + lane * 4];
        s0 += v.x; q0 += v.x * v.x;
        s1 += v.y; q1 += v.y * v.y;
        s2 += v.z; q2 += v.z * v.z;
        s3 += v.w; q3 += v.w * v.w;
    }
    __shared__ float sh[8][128];
    __shared__ float shq[8][128];
    sh[wy][lane * 4 + 0] = s0; shq[wy][lane * 4 + 0] = q0;
    sh[wy][lane * 4 + 1] = s1; shq[wy][lane * 4 + 1] = q1;
    sh[wy][lane * 4 + 2] = s2; shq[wy][lane * 4 + 2] = q2;
    sh[wy][lane * 4 + 3] = s3; shq[wy][lane * 4 + 3] = q3;
    __syncthreads();
    if (wy == 0) {
#pragma unroll
        for (int j = 0; j < 4; j++) {
            float ts = 0.f, tq = 0.f;
            for (int w = 0; w < 8; w++) { ts += sh[w][lane * 4 + j]; tq += shq[w][lane * 4 + j]; }
            atomicAdd(&g_colsum[lane * 4 + j], ts);
            atomicAdd(&g_colsq[lane * 4 + j], tq);
        }
    }
}

// ---------------- fold BN into W2 + build padded layer2 params ----------------
__global__ void prep_k(const float* __restrict__ gamma, const float* __restrict__ beta,
                       const float* __restrict__ W2,
                       const float* __restrict__ as2, const float* __restrict__ ad2) {
    int j = threadIdx.x;   // 128 threads
    __shared__ float s_scale[128], s_shift[128];
    float mean = g_colsum[j] * (1.0f / N_NODES);
    float var  = g_colsq[j] * (1.0f / N_NODES) - mean * mean;
    float sc = rsqrtf(var + 1e-5f) * gamma[j];
    s_scale[j] = sc;
    s_shift[j] = beta[j] - mean * sc;
    __syncthreads();
    int head = j >> 6, c = j & 63;
    float be = 0.f;
    if (c < 40) {
        int jo = head * 40 + c;
        for (int k = 0; k < 128; k++) {
            float w = W2[k * 80 + jo];
            g_W2p[k * 128 + j] = s_scale[k] * w;
            be += s_shift[k] * w;
        }
        g_attS2p[j] = as2[jo];
        g_attD2p[j] = ad2[jo];
    } else {
        for (int k = 0; k < 128; k++) g_W2p[k * 128 + j] = 0.f;
        g_attS2p[j] = 0.f;
        g_attD2p[j] = 0.f;
    }
    g_biasEff[j] = be;
}

// ---------------- launch ----------------
extern "C" void kernel_launch(void* const* d_in, const int* in_sizes, int n_in,
                              void* d_out, int out_size) {
    const float* x     = (const float*)d_in[0];
    const int*   ei    = (const int*)d_in[1];
    const float* W1    = (const float*)d_in[2];
    const float* as1   = (const float*)d_in[3];
    const float* ad1   = (const float*)d_in[4];
    const float* b1    = (const float*)d_in[5];
    const float* gamma = (const float*)d_in[6];
    const float* beta  = (const float*)d_in[7];
    const float* W2    = (const float*)d_in[8];
    const float* as2   = (const float*)d_in[9];
    const float* ad2   = (const float*)d_in[10];
    const float* b2    = (const float*)d_in[11];
    float* out = (float*)d_out;

    // CSR build
    init_k<<<(N_NODES + 255) / 256, 256>>>();
    count_k<<<(N_EDGES + 255) / 256, 256>>>(ei);
    scan1_k<<<SCAN_NB, 1024>>>();
    scan2_k<<<1, 32>>>();
    scan3_k<<<SCAN_NB, 1024>>>();
    fill_k<<<(TOT_E + 255) / 256, 256>>>(ei);

    const int GEMM_BLOCKS = (N_NODES + 63) / 64;   // 1563
    const int WARP_BLOCKS = (N_NODES * 32) / 256;  // 12500

    // layer 1
    gemm_k<1><<<GEMM_BLOCKS, 256>>>(x, W1, b1);
    att_k<1><<<WARP_BLOCKS, 256>>>(as1, ad1);
    agg_k<1><<<WARP_BLOCKS, 256>>>(b1, nullptr);

    // batch-norm fold
    bn_stats_k<<<256, dim3(32, 8)>>>();
    prep_k<<<1, 128>>>(gamma, beta, W2, as2, ad2);

    // layer 2 (BN folded into W2p / biasEff) + fused mean/bias/log_softmax
    gemm_k<2><<<GEMM_BLOCKS, 256>>>(nullptr, nullptr, nullptr);
    att_k<2><<<WARP_BLOCKS, 256>>>(nullptr, nullptr);
    agg_k<2><<<WARP_BLOCKS, 256>>>(b2, out);
}